// round 12
// baseline (speedup 1.0000x reference)
#include <cuda_runtime.h>
#include <cuda_fp16.h>
#include <math.h>

// ---------------------------------------------------------------------------
// Encoder_conv2: 5-level grid encoder, ONE kernel with dynamic work queue.
//  Blocks 0..4: templated per-level prep (conv3x3+tanh -> merged half-integer-
//    lattice nodes -> packed fp16 parity-pair copies -> g_G in gmem), publish
//    via fence + atomic arrival counter.
//  ALL blocks: spin until 5 levels published, copy g_G -> smem, then claim
//    1024-point chunks from a global atomic cursor and sample them
//    (per level one aligned 2x LDS.128 bilinear fetch, warp-transposed
//    coalesced stores). Dynamic chunking absorbs the prep blocks' late start.
//  Last-finishing block resets cursor/flags -> clean state for every launch /
//  graph replay. All blocks resident (grid = #SMs) -> spins cannot deadlock.
// Pair layout per level: copy A = texel pairs (2j,2j+1), copy B = (2j+1,2j+2);
// corners (m0,m0+1) are one 16B chunk at (m0&1 ? B : A) + k*rowb + (m0&~1)*8.
// Values scaled by 2^10 into fp16; 2^-10 folded exactly into blend weights.
// ---------------------------------------------------------------------------

#define GBT   125184       // sum (2r)^2 * 16 bytes (2 copies x 8B texel)

#define SCALE_UP 1024.0f
#define SCALE_DN (1.0f / 1024.0f)

// per-level compile-time constants (n2 = 2r, byte base of level in packed blob)
#define N2_(l)   ((l)==0?16:(l)==1?24:(l)==2?40:(l)==3?36:64)
#define LB_(l)   ((l)==0?0:(l)==1?4096:(l)==2?13312:(l)==3?38912:59648)

__device__ uint2 g_G[GBT / 8];   // packed grids
__device__ int   g_arrive = 0;   // prep levels published (0..5)
__device__ int   g_next   = 0;   // chunk cursor
__device__ int   g_done   = 0;   // blocks finished (for reset)

#define NTHR 1024
#define STAGE_OFF GBT
#define SMEM_TOTAL (GBT + (NTHR / 32) * 32 * 5 * 16)   // 207104 B

// ---------------------------------------------------------------------------
// templated per-level prep; sa = 2*R*R float4 scratch (block-local smem)
// ---------------------------------------------------------------------------
template<int R, int LB>
__device__ __forceinline__ void prep_level(const float* __restrict__ F,
                                           const float* w, float4* sa, int tid) {
    constexpr int RR = R * R;
    constexpr int NA = 2 * RR;
    constexpr int N2 = 2 * R;

    // conv3x3 (SAME, zero pad, cross-correlation) + tanh -> sa
    #pragma unroll 1
    for (int tex = tid; tex < NA; tex += NTHR) {
        int j  = tex / RR;
        int yx = tex - j * RR;
        int y  = yx / R;
        int x  = yx - y * R;

        float oc[4];
        #pragma unroll
        for (int c = 0; c < 4; c++) {
            float s = 0.f;
            #pragma unroll
            for (int dy = 0; dy < 3; dy++) {
                int yy = y + dy - 1;
                if (yy < 0 || yy >= R) continue;
                #pragma unroll
                for (int dx = 0; dx < 3; dx++) {
                    int xx = x + dx - 1;
                    if (xx < 0 || xx >= R) continue;
                    s += __ldg(&F[((j * 4 + c) * R + yy) * R + xx]) * w[c * 9 + dy * 3 + dx];
                }
            }
            oc[c] = tanhf(s);
        }
        sa[tex] = make_float4(oc[0], oc[1], oc[2], oc[3]);
    }
    __syncthreads();

    // merged half-lattice nodes -> packed fp16 parity-pair copies (gmem)
    uint2* lb = g_G + LB / 8;
    #pragma unroll 1
    for (int tex = tid; tex < N2 * N2; tex += NTHR) {
        int k = tex / N2;
        int m = tex - k * N2;

        float ax = 0.f, ay = 0.f, az = 0.f, aw = 0.f;
        #pragma unroll
        for (int j = 0; j < 2; j++) {
            float px = 0.5f * (float)(m + j);
            float py = 0.5f * (float)(k + j);
            float fx = floorf(px), fy = floorf(py);
            float wx = px - fx,    wy = py - fy;
            int ix0 = (int)fx, iy0 = (int)fy;
            int x0 = min(max(ix0,     0), R - 1);
            int x1 = min(max(ix0 + 1, 0), R - 1);
            int y0 = min(max(iy0,     0), R - 1);
            int y1 = min(max(iy0 + 1, 0), R - 1);
            int base = j * RR;
            float4 c00 = sa[base + y0 * R + x0];
            float4 c01 = sa[base + y0 * R + x1];
            float4 c10 = sa[base + y1 * R + x0];
            float4 c11 = sa[base + y1 * R + x1];
            float w00 = (1.f - wx) * (1.f - wy);
            float w01 = wx * (1.f - wy);
            float w10 = (1.f - wx) * wy;
            float w11 = wx * wy;
            ax += c00.x * w00 + c01.x * w01 + c10.x * w10 + c11.x * w11;
            ay += c00.y * w00 + c01.y * w01 + c10.y * w10 + c11.y * w11;
            az += c00.z * w00 + c01.z * w01 + c10.z * w10 + c11.z * w11;
            aw += c00.w * w00 + c01.w * w01 + c10.w * w10 + c11.w * w11;
        }
        __half2 h01 = __floats2half2_rn(ax * SCALE_UP, ay * SCALE_UP);
        __half2 h23 = __floats2half2_rn(az * SCALE_UP, aw * SCALE_UP);
        uint2 val;
        val.x = *reinterpret_cast<unsigned int*>(&h01);
        val.y = *reinterpret_cast<unsigned int*>(&h23);

        lb[k * N2 + m] = val;                                  // copy A
        if (m >= 1) lb[N2 * N2 + k * N2 + (m - 1)] = val;      // copy B
    }
}

// ---------------------------------------------------------------------------
__global__ void __launch_bounds__(NTHR, 1)
k_all(const float* __restrict__ F0, const float* __restrict__ F1,
      const float* __restrict__ F2, const float* __restrict__ F3,
      const float* __restrict__ F4, const float* __restrict__ W,
      const float* __restrict__ X, const float* __restrict__ Y,
      float* __restrict__ out, int npts) {
    extern __shared__ unsigned char smraw[];
    __shared__ int s_chunk;
    const int tid = threadIdx.x;

    // ---- Phase 0: blocks 0..4 build their level in g_G, publish ----
    if (blockIdx.x < 5) {
        float w[36];
        #pragma unroll
        for (int i = 0; i < 36; i++) w[i] = W[i];
        float4* sa = reinterpret_cast<float4*>(smraw + STAGE_OFF);  // conv scratch
        switch (blockIdx.x) {
            case 0: prep_level< 8, LB_(0)>(F0, w, sa, tid); break;
            case 1: prep_level<12, LB_(1)>(F1, w, sa, tid); break;
            case 2: prep_level<20, LB_(2)>(F2, w, sa, tid); break;
            case 3: prep_level<18, LB_(3)>(F3, w, sa, tid); break;
            default: prep_level<32, LB_(4)>(F4, w, sa, tid); break;
        }
        __syncthreads();
        if (tid == 0) {
            __threadfence();
            atomicAdd(&g_arrive, 1);
        }
    }

    // ---- Phase 1: wait for all levels, stage grids in smem ----
    if (tid == 0) {
        while (atomicAdd(&g_arrive, 0) < 5) __nanosleep(64);
    }
    __syncthreads();
    {
        const uint4* src = reinterpret_cast<const uint4*>(g_G);
        uint4* dst = reinterpret_cast<uint4*>(smraw);
        for (int i = tid; i < GBT / 16; i += NTHR) dst[i] = src[i];
    }
    __syncthreads();

    // ---- Phase 2: dynamic-chunk sampling ----
    const int warpid = tid >> 5;
    const int lane   = tid & 31;
    float4* wst = reinterpret_cast<float4*>(smraw + STAGE_OFF) + warpid * 160;
    float4* og  = reinterpret_cast<float4*>(out);

    while (true) {
        if (tid == 0) s_chunk = atomicAdd(&g_next, 1);
        __syncthreads();
        int p0 = s_chunk * NTHR;
        __syncthreads();               // s_chunk consumed before next overwrite
        if (p0 >= npts) break;

        int p = p0 + tid;
        if (p < npts) {
            float hx = __ldg(&X[p]);   // x in [0,1): doubled lattice coord h = x*(2r-2)
            float hy = __ldg(&Y[p]);

            #pragma unroll
            for (int l = 0; l < 5; l++) {
                const int n2         = N2_(l);
                const unsigned rowb  = (unsigned)(n2 * 8);
                const unsigned asize = (unsigned)(n2 * n2 * 8);
                const unsigned lbase = (unsigned)LB_(l);
                const float sx = (float)(n2 - 2);

                float h = hx * sx;
                float v = hy * sx;
                float fm = floorf(h), fk = floorf(v);
                int m0 = (int)fm, k0 = (int)fk;      // in-range, no clamps
                float wx = h - fm, wy = v - fk;

                unsigned addr = lbase + (unsigned)(m0 & 1) * asize
                              + (unsigned)k0 * rowb + (unsigned)(m0 & ~1) * 8u;
                uint4 t0 = *reinterpret_cast<const uint4*>(smraw + addr);         // c00,c01
                uint4 t1 = *reinterpret_cast<const uint4*>(smraw + addr + rowb);  // c10,c11

                float2 a00 = __half22float2(*reinterpret_cast<__half2*>(&t0.x));
                float2 b00 = __half22float2(*reinterpret_cast<__half2*>(&t0.y));
                float2 a01 = __half22float2(*reinterpret_cast<__half2*>(&t0.z));
                float2 b01 = __half22float2(*reinterpret_cast<__half2*>(&t0.w));
                float2 a10 = __half22float2(*reinterpret_cast<__half2*>(&t1.x));
                float2 b10 = __half22float2(*reinterpret_cast<__half2*>(&t1.y));
                float2 a11 = __half22float2(*reinterpret_cast<__half2*>(&t1.z));
                float2 b11 = __half22float2(*reinterpret_cast<__half2*>(&t1.w));

                float wyS = wy * SCALE_DN;
                float wyB = SCALE_DN - wyS;       // (1-wy)*2^-10 exactly
                float wxb = 1.f - wx;
                float w00 = wxb * wyB;
                float w01 = wx  * wyB;
                float w10 = wxb * wyS;
                float w11 = wx  * wyS;

                float4 o;
                o.x = a00.x * w00 + a01.x * w01 + a10.x * w10 + a11.x * w11;
                o.y = a00.y * w00 + a01.y * w01 + a10.y * w10 + a11.y * w11;
                o.z = b00.x * w00 + b01.x * w01 + b10.x * w10 + b11.x * w11;
                o.w = b00.y * w00 + b01.y * w01 + b10.y * w10 + b11.y * w11;

                wst[lane * 5 + l] = o;            // conflict-free STS.128
            }
        }
        __syncwarp();

        int wbase = p0 + warpid * 32;
        int cnt = npts - wbase;
        if (cnt > 0) {
            cnt = min(cnt, 32) * 5;
            float4* dst = og + (size_t)wbase * 5;
            #pragma unroll
            for (int i = 0; i < 5; i++) {
                int idx = lane + i * 32;
                if (idx < cnt) dst[idx] = wst[idx];   // fully coalesced STG.128
            }
        }
        __syncwarp();
    }

    // ---- Phase 3: last block resets queue + flags for next launch/replay ----
    if (tid == 0) {
        __threadfence();
        int d = atomicAdd(&g_done, 1);
        if (d == (int)gridDim.x - 1) {
            g_arrive = 0;
            g_next   = 0;
            g_done   = 0;
            __threadfence();
        }
    }
}

// ---------------------------------------------------------------------------
extern "C" void kernel_launch(void* const* d_in, const int* in_sizes, int n_in,
                              void* d_out, int out_size) {
    const float* X = nullptr;
    const float* Yv = nullptr;
    const float* W = nullptr;
    const float* F[5] = {nullptr, nullptr, nullptr, nullptr, nullptr};
    int npts = 0;

    for (int i = 0; i < n_in; i++) {
        int s = in_sizes[i];
        const float* p = (const float*)d_in[i];
        if (s == 36)        W    = p;
        else if (s == 512)  F[0] = p;
        else if (s == 1152) F[1] = p;
        else if (s == 3200) F[2] = p;
        else if (s == 2592) F[3] = p;
        else if (s == 8192) F[4] = p;
        else {
            if (!X) { X = p; npts = s; }
            else     Yv = p;
        }
    }

    static int nsm = 0;
    static bool init_done = false;
    if (!init_done) {
        cudaFuncSetAttribute(k_all, cudaFuncAttributeMaxDynamicSharedMemorySize, SMEM_TOTAL);
        cudaDeviceGetAttribute(&nsm, cudaDevAttrMultiProcessorCount, 0);
        if (nsm <= 0) nsm = 148;
        init_done = true;
    }

    // grid = #SMs -> all blocks resident -> spin + work queue are safe
    k_all<<<nsm, NTHR, SMEM_TOTAL>>>(F[0], F[1], F[2], F[3], F[4], W,
                                     X, Yv, (float*)d_out, npts);
}

// round 13
// speedup vs baseline: 1.2729x; 1.2729x over previous
#include <cuda_runtime.h>
#include <cuda_fp16.h>
#include <math.h>

// ---------------------------------------------------------------------------
// Encoder_conv2: 5-level grid encoder, two kernels (proven best architecture).
//  k_prep (10 blocks): per-level templated prep, node rows SLICED across
//    blocks (L0:1, L1:1, L2:2, L3:2, L4:4 blocks). Each block computes its
//    level's full conv3x3+tanh into its own smem (cheap), then builds only its
//    slice of merged half-integer-lattice node rows -> packed fp16 parity-pair
//    copies -> g_G (gmem, 125 KB).
//  k_sample (148 blocks): copy g_G -> smem, thread-per-point sampling
//    (per level one aligned 2x LDS.128 bilinear fetch), warp-transposed
//    coalesced output stores.
// Pair layout per level: copy A = texel pairs (2j,2j+1), copy B = (2j+1,2j+2);
// corners (m0,m0+1) are one 16B chunk at (m0&1 ? B : A) + k*rowb + (m0&~1)*8.
// Values scaled by 2^10 into fp16; 2^-10 folded exactly into blend weights.
// ---------------------------------------------------------------------------

#define GBT   125184       // sum (2r)^2 * 16 bytes (2 copies x 8B texel)

#define SCALE_UP 1024.0f
#define SCALE_DN (1.0f / 1024.0f)

// per-level compile-time constants (n2 = 2r, byte base of level in packed blob)
#define N2_(l)   ((l)==0?16:(l)==1?24:(l)==2?40:(l)==3?36:64)
#define LB_(l)   ((l)==0?0:(l)==1?4096:(l)==2?13312:(l)==3?38912:59648)

__device__ uint2 g_G[GBT / 8];   // packed grids, built by k_prep

// ---------------------------------------------------------------------------
// k_prep: 10 blocks; each block = (level, slice). Full conv per block
// (redundant across slices of the same level, but conv is the cheap phase),
// then only this slice's node rows.
// ---------------------------------------------------------------------------
template<int R, int LB, int SLICES>
__device__ __forceinline__ void prep_level(const float* __restrict__ F,
                                           const float* w, float4* sa,
                                           int tid, int slice) {
    constexpr int RR = R * R;
    constexpr int NA = 2 * RR;
    constexpr int N2 = 2 * R;
    constexpr int ROWS = N2 / SLICES;          // node rows per slice (divides evenly)

    // conv3x3 (SAME, zero pad, cross-correlation) + tanh -> sa (full level)
    #pragma unroll 1
    for (int tex = tid; tex < NA; tex += 1024) {
        int j  = tex / RR;
        int yx = tex - j * RR;
        int y  = yx / R;
        int x  = yx - y * R;

        float oc[4];
        #pragma unroll
        for (int c = 0; c < 4; c++) {
            float s = 0.f;
            #pragma unroll
            for (int dy = 0; dy < 3; dy++) {
                int yy = y + dy - 1;
                if (yy < 0 || yy >= R) continue;
                #pragma unroll
                for (int dx = 0; dx < 3; dx++) {
                    int xx = x + dx - 1;
                    if (xx < 0 || xx >= R) continue;
                    s += __ldg(&F[((j * 4 + c) * R + yy) * R + xx]) * w[c * 9 + dy * 3 + dx];
                }
            }
            oc[c] = tanhf(s);
        }
        sa[tex] = make_float4(oc[0], oc[1], oc[2], oc[3]);
    }
    __syncthreads();

    // this slice's node rows -> packed fp16 parity-pair copies (gmem)
    uint2* lb = g_G + LB / 8;
    const int tbeg = slice * ROWS * N2;
    const int tend = tbeg + ROWS * N2;
    #pragma unroll 1
    for (int tex = tbeg + tid; tex < tend; tex += 1024) {
        int k = tex / N2;
        int m = tex - k * N2;

        float ax = 0.f, ay = 0.f, az = 0.f, aw = 0.f;
        #pragma unroll
        for (int j = 0; j < 2; j++) {
            float px = 0.5f * (float)(m + j);
            float py = 0.5f * (float)(k + j);
            float fx = floorf(px), fy = floorf(py);
            float wx = px - fx,    wy = py - fy;
            int ix0 = (int)fx, iy0 = (int)fy;
            int x0 = min(max(ix0,     0), R - 1);
            int x1 = min(max(ix0 + 1, 0), R - 1);
            int y0 = min(max(iy0,     0), R - 1);
            int y1 = min(max(iy0 + 1, 0), R - 1);
            int base = j * RR;
            float4 c00 = sa[base + y0 * R + x0];
            float4 c01 = sa[base + y0 * R + x1];
            float4 c10 = sa[base + y1 * R + x0];
            float4 c11 = sa[base + y1 * R + x1];
            float w00 = (1.f - wx) * (1.f - wy);
            float w01 = wx * (1.f - wy);
            float w10 = (1.f - wx) * wy;
            float w11 = wx * wy;
            ax += c00.x * w00 + c01.x * w01 + c10.x * w10 + c11.x * w11;
            ay += c00.y * w00 + c01.y * w01 + c10.y * w10 + c11.y * w11;
            az += c00.z * w00 + c01.z * w01 + c10.z * w10 + c11.z * w11;
            aw += c00.w * w00 + c01.w * w01 + c10.w * w10 + c11.w * w11;
        }
        __half2 h01 = __floats2half2_rn(ax * SCALE_UP, ay * SCALE_UP);
        __half2 h23 = __floats2half2_rn(az * SCALE_UP, aw * SCALE_UP);
        uint2 val;
        val.x = *reinterpret_cast<unsigned int*>(&h01);
        val.y = *reinterpret_cast<unsigned int*>(&h23);

        lb[k * N2 + m] = val;                                  // copy A
        if (m >= 1) lb[N2 * N2 + k * N2 + (m - 1)] = val;      // copy B
    }
}

__global__ void __launch_bounds__(1024, 1)
k_prep(const float* __restrict__ F0, const float* __restrict__ F1,
       const float* __restrict__ F2, const float* __restrict__ F3,
       const float* __restrict__ F4, const float* __restrict__ W) {
    __shared__ float4 sa[2048];   // largest level: 2*32*32 texels = 32 KB
    const int tid = threadIdx.x;
    const int bid = blockIdx.x;

    float w[36];
    #pragma unroll
    for (int i = 0; i < 36; i++) w[i] = W[i];

    // block -> (level, slice): L0:1, L1:1, L2:2, L3:2, L4:4
    if      (bid == 0) prep_level< 8, LB_(0), 1>(F0, w, sa, tid, 0);
    else if (bid == 1) prep_level<12, LB_(1), 1>(F1, w, sa, tid, 0);
    else if (bid <= 3) prep_level<20, LB_(2), 2>(F2, w, sa, tid, bid - 2);
    else if (bid <= 5) prep_level<18, LB_(3), 2>(F3, w, sa, tid, bid - 4);
    else               prep_level<32, LB_(4), 4>(F4, w, sa, tid, bid - 6);
}

// ---------------------------------------------------------------------------
// k_sample: smem = packed grids (125184 B) + warp staging (81920 B).
// ---------------------------------------------------------------------------
#define NTHR 1024
#define STAGE_OFF GBT
#define SMEM_SAMPLE (GBT + (NTHR / 32) * 32 * 5 * 16)   // 207104

__global__ void __launch_bounds__(NTHR, 1)
k_sample(const float* __restrict__ X, const float* __restrict__ Y,
         float* __restrict__ out, int npts) {
    extern __shared__ unsigned char smraw[];
    const int tid = threadIdx.x;

    // coalesced copy of packed grids: 7824 uint4
    {
        const uint4* src = reinterpret_cast<const uint4*>(g_G);
        uint4* dst = reinterpret_cast<uint4*>(smraw);
        for (int i = tid; i < GBT / 16; i += NTHR) dst[i] = src[i];
    }
    __syncthreads();

    const int warpid = tid >> 5;
    const int lane   = tid & 31;
    float4* wst = reinterpret_cast<float4*>(smraw + STAGE_OFF) + warpid * 160;
    float4* og  = reinterpret_cast<float4*>(out);

    const int gstride = gridDim.x * NTHR;
    for (int p0 = blockIdx.x * NTHR; p0 < npts; p0 += gstride) {
        int p = p0 + tid;
        if (p < npts) {
            float hx = __ldg(&X[p]);   // x in [0,1): doubled lattice coord h = x*(2r-2)
            float hy = __ldg(&Y[p]);

            #pragma unroll
            for (int l = 0; l < 5; l++) {
                const int n2         = N2_(l);
                const unsigned rowb  = (unsigned)(n2 * 8);
                const unsigned asize = (unsigned)(n2 * n2 * 8);
                const unsigned lbase = (unsigned)LB_(l);
                const float sx = (float)(n2 - 2);

                float h = hx * sx;
                float v = hy * sx;
                float fm = floorf(h), fk = floorf(v);
                int m0 = (int)fm, k0 = (int)fk;      // in-range, no clamps
                float wx = h - fm, wy = v - fk;

                unsigned addr = lbase + (unsigned)(m0 & 1) * asize
                              + (unsigned)k0 * rowb + (unsigned)(m0 & ~1) * 8u;
                uint4 t0 = *reinterpret_cast<const uint4*>(smraw + addr);         // c00,c01
                uint4 t1 = *reinterpret_cast<const uint4*>(smraw + addr + rowb);  // c10,c11

                float2 a00 = __half22float2(*reinterpret_cast<__half2*>(&t0.x));
                float2 b00 = __half22float2(*reinterpret_cast<__half2*>(&t0.y));
                float2 a01 = __half22float2(*reinterpret_cast<__half2*>(&t0.z));
                float2 b01 = __half22float2(*reinterpret_cast<__half2*>(&t0.w));
                float2 a10 = __half22float2(*reinterpret_cast<__half2*>(&t1.x));
                float2 b10 = __half22float2(*reinterpret_cast<__half2*>(&t1.y));
                float2 a11 = __half22float2(*reinterpret_cast<__half2*>(&t1.z));
                float2 b11 = __half22float2(*reinterpret_cast<__half2*>(&t1.w));

                float wyS = wy * SCALE_DN;
                float wyB = SCALE_DN - wyS;       // (1-wy)*2^-10 exactly
                float wxb = 1.f - wx;
                float w00 = wxb * wyB;
                float w01 = wx  * wyB;
                float w10 = wxb * wyS;
                float w11 = wx  * wyS;

                float4 o;
                o.x = a00.x * w00 + a01.x * w01 + a10.x * w10 + a11.x * w11;
                o.y = a00.y * w00 + a01.y * w01 + a10.y * w10 + a11.y * w11;
                o.z = b00.x * w00 + b01.x * w01 + b10.x * w10 + b11.x * w11;
                o.w = b00.y * w00 + b01.y * w01 + b10.y * w10 + b11.y * w11;

                wst[lane * 5 + l] = o;            // conflict-free STS.128
            }
        }
        __syncwarp();

        int wbase = p0 + warpid * 32;
        int cnt = npts - wbase;
        if (cnt > 0) {
            cnt = min(cnt, 32) * 5;
            float4* dst = og + (size_t)wbase * 5;
            #pragma unroll
            for (int i = 0; i < 5; i++) {
                int idx = lane + i * 32;
                if (idx < cnt) dst[idx] = wst[idx];   // fully coalesced STG.128
            }
        }
        __syncwarp();
    }
}

// ---------------------------------------------------------------------------
extern "C" void kernel_launch(void* const* d_in, const int* in_sizes, int n_in,
                              void* d_out, int out_size) {
    const float* X = nullptr;
    const float* Yv = nullptr;
    const float* W = nullptr;
    const float* F[5] = {nullptr, nullptr, nullptr, nullptr, nullptr};
    int npts = 0;

    for (int i = 0; i < n_in; i++) {
        int s = in_sizes[i];
        const float* p = (const float*)d_in[i];
        if (s == 36)        W    = p;
        else if (s == 512)  F[0] = p;
        else if (s == 1152) F[1] = p;
        else if (s == 3200) F[2] = p;
        else if (s == 2592) F[3] = p;
        else if (s == 8192) F[4] = p;
        else {
            if (!X) { X = p; npts = s; }
            else     Yv = p;
        }
    }

    static int nsm = 0;
    static bool init_done = false;
    if (!init_done) {
        cudaFuncSetAttribute(k_sample, cudaFuncAttributeMaxDynamicSharedMemorySize, SMEM_SAMPLE);
        cudaDeviceGetAttribute(&nsm, cudaDevAttrMultiProcessorCount, 0);
        if (nsm <= 0) nsm = 148;
        init_done = true;
    }

    k_prep<<<10, 1024>>>(F[0], F[1], F[2], F[3], F[4], W);
    k_sample<<<nsm, NTHR, SMEM_SAMPLE>>>(X, Yv, (float*)d_out, npts);
}

// round 14
// speedup vs baseline: 1.3500x; 1.0606x over previous
#include <cuda_runtime.h>
#include <cuda_fp16.h>
#include <math.h>

// ---------------------------------------------------------------------------
// Encoder_conv2: 5-level grid encoder, two kernels.
//  k_prep (10 blocks): per-level templated prep, node rows sliced across
//    blocks (L0:1, L1:1, L2:2, L3:2, L4:4). conv3x3+tanh -> smem -> merged
//    half-integer-lattice nodes -> packed fp16 parity-pair copies -> g_G.
//  k_sample (148 blocks): copy g_G -> smem; (point,level)-per-thread-slot
//    mapping: store step s, lane writes output float4 wb*5+s*32+lane
//    (fully coalesced STG.128 straight from registers, NO staging).
//    Per-slot q=(s*32+lane)/5 and level constants are loop-invariant and
//    precomputed in registers.
// Pair layout per level: copy A = texel pairs (2j,2j+1), copy B = (2j+1,2j+2);
// corners (m0,m0+1) are one 16B chunk at (m0&1 ? B : A) + k*rowb + (m0&~1)*8.
// Values scaled by 2^10 into fp16; 2^-10 folded exactly into blend weights.
// ---------------------------------------------------------------------------

#define GBT   125184       // sum (2r)^2 * 16 bytes (2 copies x 8B texel)

#define SCALE_UP 1024.0f
#define SCALE_DN (1.0f / 1024.0f)

#define LB_(l)   ((l)==0?0:(l)==1?4096:(l)==2?13312:(l)==3?38912:59648)

__device__ uint2 g_G[GBT / 8];   // packed grids, built by k_prep

// ---------------------------------------------------------------------------
// k_prep: 10 blocks; block = (level, slice). Full conv per block (cheap),
// then only this slice's node rows.
// ---------------------------------------------------------------------------
template<int R, int LB, int SLICES>
__device__ __forceinline__ void prep_level(const float* __restrict__ F,
                                           const float* w, float4* sa,
                                           int tid, int slice) {
    constexpr int RR = R * R;
    constexpr int NA = 2 * RR;
    constexpr int N2 = 2 * R;
    constexpr int ROWS = N2 / SLICES;

    #pragma unroll 1
    for (int tex = tid; tex < NA; tex += 1024) {
        int j  = tex / RR;
        int yx = tex - j * RR;
        int y  = yx / R;
        int x  = yx - y * R;

        float oc[4];
        #pragma unroll
        for (int c = 0; c < 4; c++) {
            float s = 0.f;
            #pragma unroll
            for (int dy = 0; dy < 3; dy++) {
                int yy = y + dy - 1;
                if (yy < 0 || yy >= R) continue;
                #pragma unroll
                for (int dx = 0; dx < 3; dx++) {
                    int xx = x + dx - 1;
                    if (xx < 0 || xx >= R) continue;
                    s += __ldg(&F[((j * 4 + c) * R + yy) * R + xx]) * w[c * 9 + dy * 3 + dx];
                }
            }
            oc[c] = tanhf(s);
        }
        sa[tex] = make_float4(oc[0], oc[1], oc[2], oc[3]);
    }
    __syncthreads();

    uint2* lb = g_G + LB / 8;
    const int tbeg = slice * ROWS * N2;
    const int tend = tbeg + ROWS * N2;
    #pragma unroll 1
    for (int tex = tbeg + tid; tex < tend; tex += 1024) {
        int k = tex / N2;
        int m = tex - k * N2;

        float ax = 0.f, ay = 0.f, az = 0.f, aw = 0.f;
        #pragma unroll
        for (int j = 0; j < 2; j++) {
            float px = 0.5f * (float)(m + j);
            float py = 0.5f * (float)(k + j);
            float fx = floorf(px), fy = floorf(py);
            float wx = px - fx,    wy = py - fy;
            int ix0 = (int)fx, iy0 = (int)fy;
            int x0 = min(max(ix0,     0), R - 1);
            int x1 = min(max(ix0 + 1, 0), R - 1);
            int y0 = min(max(iy0,     0), R - 1);
            int y1 = min(max(iy0 + 1, 0), R - 1);
            int base = j * RR;
            float4 c00 = sa[base + y0 * R + x0];
            float4 c01 = sa[base + y0 * R + x1];
            float4 c10 = sa[base + y1 * R + x0];
            float4 c11 = sa[base + y1 * R + x1];
            float w00 = (1.f - wx) * (1.f - wy);
            float w01 = wx * (1.f - wy);
            float w10 = (1.f - wx) * wy;
            float w11 = wx * wy;
            ax += c00.x * w00 + c01.x * w01 + c10.x * w10 + c11.x * w11;
            ay += c00.y * w00 + c01.y * w01 + c10.y * w10 + c11.y * w11;
            az += c00.z * w00 + c01.z * w01 + c10.z * w10 + c11.z * w11;
            aw += c00.w * w00 + c01.w * w01 + c10.w * w10 + c11.w * w11;
        }
        __half2 h01 = __floats2half2_rn(ax * SCALE_UP, ay * SCALE_UP);
        __half2 h23 = __floats2half2_rn(az * SCALE_UP, aw * SCALE_UP);
        uint2 val;
        val.x = *reinterpret_cast<unsigned int*>(&h01);
        val.y = *reinterpret_cast<unsigned int*>(&h23);

        lb[k * N2 + m] = val;                                  // copy A
        if (m >= 1) lb[N2 * N2 + k * N2 + (m - 1)] = val;      // copy B
    }
}

__global__ void __launch_bounds__(1024, 1)
k_prep(const float* __restrict__ F0, const float* __restrict__ F1,
       const float* __restrict__ F2, const float* __restrict__ F3,
       const float* __restrict__ F4, const float* __restrict__ W) {
    __shared__ float4 sa[2048];
    const int tid = threadIdx.x;
    const int bid = blockIdx.x;

    float w[36];
    #pragma unroll
    for (int i = 0; i < 36; i++) w[i] = W[i];

    if      (bid == 0) prep_level< 8, LB_(0), 1>(F0, w, sa, tid, 0);
    else if (bid == 1) prep_level<12, LB_(1), 1>(F1, w, sa, tid, 0);
    else if (bid <= 3) prep_level<20, LB_(2), 2>(F2, w, sa, tid, bid - 2);
    else if (bid <= 5) prep_level<18, LB_(3), 2>(F3, w, sa, tid, bid - 4);
    else               prep_level<32, LB_(4), 4>(F4, w, sa, tid, bid - 6);
}

// ---------------------------------------------------------------------------
// k_sample: smem = packed grids only (125184 B).
// (point,level)-per-thread-slot mapping; coalesced register stores.
// ---------------------------------------------------------------------------
#define NTHR 1024

__global__ void __launch_bounds__(NTHR, 1)
k_sample(const float* __restrict__ X, const float* __restrict__ Y,
         float* __restrict__ out, int npts) {
    extern __shared__ unsigned char smraw[];
    const int tid = threadIdx.x;

    // coalesced copy of packed grids: 7824 uint4
    {
        const uint4* src = reinterpret_cast<const uint4*>(g_G);
        uint4* dst = reinterpret_cast<uint4*>(smraw);
        for (int i = tid; i < GBT / 16; i += NTHR) dst[i] = src[i];
    }
    __syncthreads();

    const int warpid = tid >> 5;
    const int lane   = tid & 31;

    // loop-invariant per-slot state: q = (s*32+lane)/5, level consts packed
    int      qoff_[5];
    float    sx_[5];
    unsigned lr_[5];          // lbase | (rowb << 16);  asize = rowb*rowb/8
    #pragma unroll
    for (int s = 0; s < 5; s++) {
        int j = s * 32 + lane;
        int q = j / 5;
        int l = j - q * 5;
        qoff_[s] = q;
        int n2 = (l == 0) ? 16 : (l == 1) ? 24 : (l == 2) ? 40 : (l == 3) ? 36 : 64;
        unsigned lbase = (l == 0) ? 0u : (l == 1) ? 4096u : (l == 2) ? 13312u
                       : (l == 3) ? 38912u : 59648u;
        sx_[s] = (float)(n2 - 2);
        lr_[s] = lbase | ((unsigned)(n2 * 8) << 16);
    }

    float4* og = reinterpret_cast<float4*>(out);
    const int gstride = gridDim.x * NTHR;

    for (int p0 = blockIdx.x * NTHR; p0 < npts; p0 += gstride) {
        int wb = p0 + warpid * 32;          // this warp's 32-point window
        if (wb >= npts) break;
        size_t ob = (size_t)wb * 5 + lane;  // store base (float4 units)

        #pragma unroll
        for (int s = 0; s < 5; s++) {
            int p = wb + qoff_[s];
            if (p < npts) {
                float hx = __ldg(&X[p]);    // x in [0,1): h = x*(2r-2)
                float hy = __ldg(&Y[p]);

                unsigned lr    = lr_[s];
                unsigned lbase = lr & 0xFFFFu;
                unsigned rowb  = lr >> 16;
                unsigned asize = (rowb * rowb) >> 3;   // n2*n2*8
                float sx = sx_[s];

                float h = hx * sx;
                float v = hy * sx;
                float fm = floorf(h), fk = floorf(v);
                int m0 = (int)fm, k0 = (int)fk;        // in-range, no clamps
                float wx = h - fm, wy = v - fk;

                unsigned addr = lbase + (unsigned)(m0 & 1) * asize
                              + (unsigned)k0 * rowb + (unsigned)(m0 & ~1) * 8u;
                uint4 t0 = *reinterpret_cast<const uint4*>(smraw + addr);         // c00,c01
                uint4 t1 = *reinterpret_cast<const uint4*>(smraw + addr + rowb);  // c10,c11

                float2 a00 = __half22float2(*reinterpret_cast<__half2*>(&t0.x));
                float2 b00 = __half22float2(*reinterpret_cast<__half2*>(&t0.y));
                float2 a01 = __half22float2(*reinterpret_cast<__half2*>(&t0.z));
                float2 b01 = __half22float2(*reinterpret_cast<__half2*>(&t0.w));
                float2 a10 = __half22float2(*reinterpret_cast<__half2*>(&t1.x));
                float2 b10 = __half22float2(*reinterpret_cast<__half2*>(&t1.y));
                float2 a11 = __half22float2(*reinterpret_cast<__half2*>(&t1.z));
                float2 b11 = __half22float2(*reinterpret_cast<__half2*>(&t1.w));

                float wyS = wy * SCALE_DN;
                float wyB = SCALE_DN - wyS;            // (1-wy)*2^-10 exactly
                float wxb = 1.f - wx;
                float w00 = wxb * wyB;
                float w01 = wx  * wyB;
                float w10 = wxb * wyS;
                float w11 = wx  * wyS;

                float4 o;
                o.x = a00.x * w00 + a01.x * w01 + a10.x * w10 + a11.x * w11;
                o.y = a00.y * w00 + a01.y * w01 + a10.y * w10 + a11.y * w11;
                o.z = b00.x * w00 + b01.x * w01 + b10.x * w10 + b11.x * w11;
                o.w = b00.y * w00 + b01.y * w01 + b10.y * w10 + b11.y * w11;

                og[ob + s * 32] = o;        // fully coalesced STG.128
            }
        }
    }
}

// ---------------------------------------------------------------------------
extern "C" void kernel_launch(void* const* d_in, const int* in_sizes, int n_in,
                              void* d_out, int out_size) {
    const float* X = nullptr;
    const float* Yv = nullptr;
    const float* W = nullptr;
    const float* F[5] = {nullptr, nullptr, nullptr, nullptr, nullptr};
    int npts = 0;

    for (int i = 0; i < n_in; i++) {
        int s = in_sizes[i];
        const float* p = (const float*)d_in[i];
        if (s == 36)        W    = p;
        else if (s == 512)  F[0] = p;
        else if (s == 1152) F[1] = p;
        else if (s == 3200) F[2] = p;
        else if (s == 2592) F[3] = p;
        else if (s == 8192) F[4] = p;
        else {
            if (!X) { X = p; npts = s; }
            else     Yv = p;
        }
    }

    static int nsm = 0;
    static bool init_done = false;
    if (!init_done) {
        cudaFuncSetAttribute(k_sample, cudaFuncAttributeMaxDynamicSharedMemorySize, GBT);
        cudaDeviceGetAttribute(&nsm, cudaDevAttrMultiProcessorCount, 0);
        if (nsm <= 0) nsm = 148;
        init_done = true;
    }

    k_prep<<<10, 1024>>>(F[0], F[1], F[2], F[3], F[4], W);
    k_sample<<<nsm, NTHR, GBT>>>(X, Yv, (float*)d_out, npts);
}